// round 13
// baseline (speedup 1.0000x reference)
#include <cuda_runtime.h>
#include <cstdint>

#define BB 4
#define CC 192
#define NN 4096
#define KK 9
#define NCAND 16
#define PADL 136

__device__ __align__(256) float g_xn[(size_t)BB * CC * NN];   // normalized pts [b][c][n]
__device__ __align__(256) float g_sq[(size_t)BB * NN];        // per-point sum of squares
__device__ __align__(256) float g_dist[(size_t)BB * NN * NN]; // tf32 distance matrix
__device__ __align__(256) int   g_cand[(size_t)BB * NN * NCAND];

__device__ __forceinline__ void cp_async16(void* smem_dst, const void* gmem_src) {
    unsigned saddr = (unsigned)__cvta_generic_to_shared(smem_dst);
    asm volatile("cp.async.ca.shared.global [%0], [%1], 16;\n" :: "r"(saddr), "l"(gmem_src));
}
__device__ __forceinline__ void cp_commit() {
    asm volatile("cp.async.commit_group;\n");
}
template <int N>
__device__ __forceinline__ void cp_wait() {
    asm volatile("cp.async.wait_group %0;\n" :: "n"(N));
}

__device__ __forceinline__ void mma_tf32(float* c, const uint32_t* a, const uint32_t* b) {
    asm volatile(
        "mma.sync.aligned.m16n8k8.row.col.f32.tf32.tf32.f32 "
        "{%0,%1,%2,%3}, {%4,%5,%6,%7}, {%8,%9}, {%0,%1,%2,%3};"
        : "+f"(c[0]), "+f"(c[1]), "+f"(c[2]), "+f"(c[3])
        : "r"(a[0]), "r"(a[1]), "r"(a[2]), "r"(a[3]), "r"(b[0]), "r"(b[1]));
}

// ---------------------------------------------------------------------------
// Kernel 1: L2-normalize over channel dim. x layout [B][C][N], N = H*W.
// ---------------------------------------------------------------------------
__global__ void normalize_kernel(const float* __restrict__ x) {
    int b = blockIdx.y;
    int n = blockIdx.x * blockDim.x + threadIdx.x;
    if (n >= NN) return;
    const float* xb = x + (size_t)b * CC * NN + n;
    float s = 0.f;
    #pragma unroll 16
    for (int c = 0; c < CC; c++) { float v = xb[(size_t)c * NN]; s += v * v; }
    float denom = fmaxf(sqrtf(s), 1e-12f);
    float* xnb = g_xn + (size_t)b * CC * NN + n;
    float sq = 0.f;
    #pragma unroll 16
    for (int c = 0; c < CC; c++) {
        float p = xb[(size_t)c * NN] / denom;
        xnb[(size_t)c * NN] = p;
        sq += p * p;
    }
    g_sq[(size_t)b * NN + n] = sq;
}

// ---------------------------------------------------------------------------
// Kernel 2: symmetric tf32 tensor-core distance GEMM (candidate-quality).
// 128x128 tile, 8 warps (2x4), warp tile 64x32, mma m16n8k8 tf32.
// cp.async double-buffered k-chunks of 8. Mirror tile via smem transpose.
// ---------------------------------------------------------------------------
__global__ __launch_bounds__(256) void dist_gemm_tf32_kernel() {
    __shared__ union {
        float ab[2][2][8][PADL];   // [buf][A/B][k][col]  -> 34.8 KB
        float ts[128 * 33];        // transpose staging   -> 16.9 KB
    } sm;

    int u = blockIdx.x;
    int bi = 0, rowlen = 32;
    while (u >= rowlen) { u -= rowlen; rowlen--; bi++; }
    const int bj = bi + u;

    const int b  = blockIdx.z;
    const int n0 = bi * 128;
    const int m0 = bj * 128;
    const float* base = g_xn + (size_t)b * CC * NN;
    const int tid  = threadIdx.x;
    const int lane = tid & 31;
    const int w    = tid >> 5;
    const int wr = (w & 1) * 64;    // warp row base (n dir)
    const int wc = (w >> 1) * 32;   // warp col base (m dir)

    // loader: thread -> k-row (tid>>5), float4 col slot (lane*4)
    const int lr = tid >> 5;
    const int lc = lane * 4;

    {
        const float* s = base + (size_t)lr * NN;
        cp_async16(&sm.ab[0][0][lr][lc], s + n0 + lc);
        cp_async16(&sm.ab[0][1][lr][lc], s + m0 + lc);
        cp_commit();
    }

    float acc[4][4][4];
    #pragma unroll
    for (int i = 0; i < 4; i++)
        #pragma unroll
        for (int j = 0; j < 4; j++)
            #pragma unroll
            for (int q = 0; q < 4; q++) acc[i][j][q] = 0.f;

    const int NT = CC / 8;   // 24
    #pragma unroll 1
    for (int t = 0; t < NT; t++) {
        const int cur = t & 1;
        if (t + 1 < NT) {
            const float* s = base + (size_t)((t + 1) * 8 + lr) * NN;
            cp_async16(&sm.ab[cur ^ 1][0][lr][lc], s + n0 + lc);
            cp_async16(&sm.ab[cur ^ 1][1][lr][lc], s + m0 + lc);
            cp_commit();
            cp_wait<1>();
        } else {
            cp_wait<0>();
        }
        __syncthreads();

        const float (*As)[PADL] = sm.ab[cur][0];
        const float (*Bs)[PADL] = sm.ab[cur][1];
        const int r0 = lane >> 2;
        const int k0 = lane & 3;

        uint32_t afr[4][4], bfr[4][2];
        #pragma unroll
        for (int wm = 0; wm < 4; wm++) {
            int rb = wr + wm * 16 + r0;
            afr[wm][0] = __float_as_uint(As[k0][rb]);
            afr[wm][1] = __float_as_uint(As[k0][rb + 8]);
            afr[wm][2] = __float_as_uint(As[k0 + 4][rb]);
            afr[wm][3] = __float_as_uint(As[k0 + 4][rb + 8]);
        }
        #pragma unroll
        for (int wn = 0; wn < 4; wn++) {
            int cb = wc + wn * 8 + r0;
            bfr[wn][0] = __float_as_uint(Bs[k0][cb]);
            bfr[wn][1] = __float_as_uint(Bs[k0 + 4][cb]);
        }
        #pragma unroll
        for (int wm = 0; wm < 4; wm++)
            #pragma unroll
            for (int wn = 0; wn < 4; wn++)
                mma_tf32(acc[wm][wn], afr[wm], bfr[wn]);
        __syncthreads();
    }

    const float* sqb = g_sq + (size_t)b * NN;

    // ---- normal tile: dist[n][m] = (sq_n + (-2*dot)) + sq_m ----
    #pragma unroll
    for (int wm = 0; wm < 4; wm++) {
        int rg = n0 + wr + wm * 16 + (lane >> 2);
        float sqn0 = sqb[rg], sqn1 = sqb[rg + 8];
        #pragma unroll
        for (int wn = 0; wn < 4; wn++) {
            int cg = m0 + wc + wn * 8 + (lane & 3) * 2;
            float sqm0 = sqb[cg], sqm1 = sqb[cg + 1];
            float* p0 = g_dist + ((size_t)b * NN + rg) * NN + cg;
            float* p1 = g_dist + ((size_t)b * NN + rg + 8) * NN + cg;
            p0[0] = (sqn0 + (-2.f * acc[wm][wn][0])) + sqm0;
            p0[1] = (sqn0 + (-2.f * acc[wm][wn][1])) + sqm1;
            p1[0] = (sqn1 + (-2.f * acc[wm][wn][2])) + sqm0;
            p1[1] = (sqn1 + (-2.f * acc[wm][wn][3])) + sqm1;
        }
    }

    // ---- mirrored tile: dist[m][n] = (sq_m + (-2*dot)) + sq_n ----
    if (bi != bj) {
        #pragma unroll 1
        for (int c = 0; c < 4; c++) {           // m'-chunks of 32 = warp_col c
            __syncthreads();
            if ((wc >> 5) == c) {
                #pragma unroll
                for (int wm = 0; wm < 4; wm++) {
                    int rl = wr + wm * 16 + (lane >> 2);
                    #pragma unroll
                    for (int wn = 0; wn < 4; wn++) {
                        int cl = wn * 8 + (lane & 3) * 2;
                        sm.ts[(size_t)rl * 33 + cl]           = acc[wm][wn][0];
                        sm.ts[(size_t)rl * 33 + cl + 1]       = acc[wm][wn][1];
                        sm.ts[(size_t)(rl + 8) * 33 + cl]     = acc[wm][wn][2];
                        sm.ts[(size_t)(rl + 8) * 33 + cl + 1] = acc[wm][wn][3];
                    }
                }
            }
            __syncthreads();
            int rbase = tid >> 5;
            #pragma unroll
            for (int rr = 0; rr < 4; rr++) {
                int r = rr * 8 + rbase;          // 0..31
                int m = m0 + c * 32 + r;
                float sqm_v = sqb[m];
                float* drow = g_dist + ((size_t)b * NN + m) * NN + n0;
                #pragma unroll
                for (int wv = 0; wv < 4; wv++) {
                    int col = lane + 32 * wv;
                    float tval = sm.ts[(size_t)col * 33 + r];
                    drow[col] = (sqm_v + (-2.f * tval)) + sqb[n0 + col];
                }
            }
        }
    }
}

// ---------------------------------------------------------------------------
// Kernel 3: warp-per-row top-17 on tf32 distances -> 16 non-self candidates.
// ---------------------------------------------------------------------------
__device__ __forceinline__ unsigned ford(float f) {
    unsigned u = __float_as_uint(f);
    return (u & 0x80000000u) ? ~u : (u | 0x80000000u);
}

__global__ void select_cand_kernel() {
    const int warp = (blockIdx.x * blockDim.x + threadIdx.x) >> 5;
    const int lane = threadIdx.x & 31;
    if (warp >= BB * NN) return;
    const int row = warp;
    const int n = row & (NN - 1);
    const float* drow = g_dist + (size_t)row * NN;

    float v[17]; int id[17];
    #pragma unroll
    for (int k = 0; k < 17; k++) { v[k] = 3.4e38f; id[k] = 0x7FFFFFFF; }

    for (int m = lane; m < NN; m += 32) {
        float val = drow[m];
        if ((val < v[16]) || (val == v[16] && m < id[16])) {
            v[16] = val; id[16] = m;
            #pragma unroll
            for (int k = 16; k > 0; k--) {
                bool sw = (v[k] < v[k-1]) || (v[k] == v[k-1] && id[k] < id[k-1]);
                if (sw) {
                    float tv = v[k]; v[k] = v[k-1]; v[k-1] = tv;
                    int ti = id[k]; id[k] = id[k-1]; id[k-1] = ti;
                }
            }
        }
    }

    int pos = 0, wcount = 0;
    for (int r = 0; r < 17; r++) {
        unsigned long long myk = (pos < 17)
            ? (((unsigned long long)ford(v[pos]) << 32) | (unsigned)id[pos])
            : 0xFFFFFFFFFFFFFFFFULL;
        unsigned long long mn = myk;
        #pragma unroll
        for (int off = 16; off > 0; off >>= 1) {
            unsigned long long o = __shfl_xor_sync(0xFFFFFFFFu, mn, off);
            mn = (o < mn) ? o : mn;
        }
        if (myk == mn) pos++;
        if (lane == 0) {
            int idv = (int)(mn & 0xFFFFFFFFu);
            if (idv != n && wcount < NCAND)
                g_cand[(size_t)row * NCAND + wcount++] = idv;
        }
    }
}

// ---------------------------------------------------------------------------
// Kernel 4: exact fp32 rescore of 16 candidates (serial c-ascending FFMA,
// bit-identical to the round-8 fp32 GEMM), final top-9 + edge emission.
// ---------------------------------------------------------------------------
__global__ void rescore_kernel(float* __restrict__ out) {
    const int warp = (blockIdx.x * blockDim.x + threadIdx.x) >> 5;
    const int lane = threadIdx.x & 31;
    if (warp >= BB * NN) return;
    const int row = warp;
    const int b = row >> 12;
    const int n = row & (NN - 1);
    const float* base = g_xn + (size_t)b * CC * NN;
    const float* sqb  = g_sq + (size_t)b * NN;

    unsigned long long key = 0xFFFFFFFFFFFFFFFFULL;
    if (lane < NCAND) {
        int m = g_cand[(size_t)row * NCAND + lane];
        float acc = 0.f;
        #pragma unroll 8
        for (int c = 0; c < CC; c++)
            acc = fmaf(base[(size_t)c * NN + n], base[(size_t)c * NN + m], acc);
        float d = (sqb[n] + (-2.0f * acc)) + sqb[m];
        key = ((unsigned long long)ford(d) << 32) | (unsigned)m;
    }

    const size_t L = (size_t)BB * NN * KK;
    const size_t outbase = (size_t)row * KK;
    for (int k = 0; k < KK; k++) {
        unsigned long long mn = key;
        #pragma unroll
        for (int off = 16; off > 0; off >>= 1) {
            unsigned long long o = __shfl_xor_sync(0xFFFFFFFFu, mn, off);
            mn = (o < mn) ? o : mn;
        }
        if (key == mn) key = 0xFFFFFFFFFFFFFFFFULL;   // remove winner
        if (lane == 0)
            out[outbase + k] = (float)((int)(mn & 0xFFFFFFFFu) + b * NN);
    }
    if (lane < KK) out[L + outbase + lane] = (float)(n + b * NN);
}

// ---------------------------------------------------------------------------
extern "C" void kernel_launch(void* const* d_in, const int* in_sizes, int n_in,
                              void* d_out, int out_size) {
    const float* x = (const float*)d_in[0];
    float* out = (float*)d_out;

    { dim3 grid(NN / 256, BB); normalize_kernel<<<grid, 256>>>(x); }
    { dim3 grid(528, 1, BB); dist_gemm_tf32_kernel<<<grid, 256>>>(); }
    { int rows = BB * NN; select_cand_kernel<<<(rows * 32 + 255) / 256, 256>>>(); }
    { int rows = BB * NN; rescore_kernel<<<(rows * 32 + 255) / 256, 256>>>(out); }
}